// round 1
// baseline (speedup 1.0000x reference)
#include <cuda_runtime.h>
#include <cuda_bf16.h>

// Problem constants
#define NC 4
#define NN 512
#define ED 512
#define PD 64
#define NH 32
#define HD 16

// Attention kernel tiling
#define IB 4      // query rows per block
#define JT 32     // key rows per j-tile
#define KS 516    // ksh row stride (pad for bank conflicts)
#define PS 68     // pbar row stride

// Scratch (static __device__ arrays; no allocations allowed)
__device__ float g_xq[NC * NN * ED];
__device__ float g_q [NC * NN * ED];
__device__ float g_k [NC * NN * ED];
__device__ float g_v [NC * NN * ED];
__device__ float g_vf[NC * NH * NN];

// ---------------------------------------------------------------------------
// Kernel A: LayerNorm(query) -> g_xq.  One block per row (2048 rows of 512).
// ---------------------------------------------------------------------------
__global__ void ln_q_kernel(const float* __restrict__ x,
                            const float* __restrict__ g,
                            const float* __restrict__ b) {
    int row = blockIdx.x;
    const float* xr = x + (size_t)row * ED;
    float* o = g_xq + (size_t)row * ED;
    int tid = threadIdx.x;  // 128 threads
    float v[4];
    float s = 0.f, s2 = 0.f;
#pragma unroll
    for (int t = 0; t < 4; t++) {
        float vv = xr[tid + t * 128];
        v[t] = vv; s += vv; s2 += vv * vv;
    }
#pragma unroll
    for (int off = 16; off; off >>= 1) {
        s  += __shfl_down_sync(0xffffffffu, s,  off);
        s2 += __shfl_down_sync(0xffffffffu, s2, off);
    }
    __shared__ float sh[8];
    if ((tid & 31) == 0) { sh[tid >> 5] = s; sh[4 + (tid >> 5)] = s2; }
    __syncthreads();
    float S  = sh[0] + sh[1] + sh[2] + sh[3];
    float S2 = sh[4] + sh[5] + sh[6] + sh[7];
    float mu   = S * (1.f / ED);
    float var  = S2 * (1.f / ED) - mu * mu;
    float rstd = rsqrtf(var + 1e-5f);
#pragma unroll
    for (int t = 0; t < 4; t++) {
        int e = tid + t * 128;
        o[e] = (v[t] - mu) * rstd * g[e] + b[e];
    }
}

// ---------------------------------------------------------------------------
// Kernel B: QKV projection GEMM.  O[m][o] = sum_e xq[m][e] * W[o][e]  (NT form)
// M=2048, N=512, K=512, blockIdx.z selects {Q(scale .25), K, V}.
// 64x64 tile, BK=16, 256 threads, 4x4 micro-tile.
// ---------------------------------------------------------------------------
__global__ void __launch_bounds__(256) qkv_gemm(
    const float* __restrict__ Wq, const float* __restrict__ Wk,
    const float* __restrict__ Wv) {
    const float* W; float* O; float scale = 1.f;
    if (blockIdx.z == 0)      { W = Wq; O = g_q; scale = 0.25f; }  // D^-0.5 = 16^-0.5
    else if (blockIdx.z == 1) { W = Wk; O = g_k; }
    else                      { W = Wv; O = g_v; }
    const float* A = g_xq;

    __shared__ float As[16][65];
    __shared__ float Bs[16][65];
    int tid = threadIdx.x;
    int tx = tid & 15, ty = tid >> 4;
    int m0 = blockIdx.y * 64, n0 = blockIdx.x * 64;
    float acc[4][4] = {};
    int lr = tid >> 2;          // 0..63
    int lk = (tid & 3) * 4;     // 0,4,8,12

    for (int k0 = 0; k0 < ED; k0 += 16) {
        float4 av = *(const float4*)&A[(size_t)(m0 + lr) * ED + k0 + lk];
        float4 bv = *(const float4*)&W[(size_t)(n0 + lr) * ED + k0 + lk];
        As[lk + 0][lr] = av.x; As[lk + 1][lr] = av.y;
        As[lk + 2][lr] = av.z; As[lk + 3][lr] = av.w;
        Bs[lk + 0][lr] = bv.x; Bs[lk + 1][lr] = bv.y;
        Bs[lk + 2][lr] = bv.z; Bs[lk + 3][lr] = bv.w;
        __syncthreads();
#pragma unroll
        for (int kk = 0; kk < 16; kk++) {
            float ar[4], br[4];
#pragma unroll
            for (int i = 0; i < 4; i++) { ar[i] = As[kk][ty * 4 + i]; br[i] = Bs[kk][tx * 4 + i]; }
#pragma unroll
            for (int i = 0; i < 4; i++)
#pragma unroll
                for (int j = 0; j < 4; j++) acc[i][j] += ar[i] * br[j];
        }
        __syncthreads();
    }
#pragma unroll
    for (int i = 0; i < 4; i++)
#pragma unroll
        for (int j = 0; j < 4; j++)
            O[(size_t)(m0 + ty * 4 + i) * ED + n0 + tx * 4 + j] = acc[i][j] * scale;
}

// ---------------------------------------------------------------------------
// Kernel C: vf[c,h,j] = sum_d v[c,h,j,d] * Wf[h*16+d]
// ---------------------------------------------------------------------------
__global__ void vf_kernel(const float* __restrict__ Wf) {
    int idx = blockIdx.x * blockDim.x + threadIdx.x;  // over NC*NN*NH = 65536
    int c   = idx / (NN * NH);
    int rem = idx - c * NN * NH;
    int j = rem >> 5;
    int h = rem & 31;
    const float* vr = g_v + ((size_t)(c * NN) + j) * ED + h * HD;
    const float* wf = Wf + h * HD;
    float s = 0.f;
#pragma unroll
    for (int d = 0; d < HD; d++) s += vr[d] * wf[d];
    g_vf[(size_t)(c * NH + h) * NN + j] = s;
}

// ---------------------------------------------------------------------------
// Kernel D: fused pair-LN + bias + attention softmax (online) + force.
// Block = (i-tile of IB rows, chain c).  256 threads = 32 heads x 8 j-lanes.
// force[c,i,r] = sum_j delta[c,i,j,r] * sum_h probs[c,h,i,j] * vf[c,h,j]
// ---------------------------------------------------------------------------
__global__ void __launch_bounds__(256) attn_force_kernel(
    const float* __restrict__ pair, const float* __restrict__ delta,
    const float* __restrict__ lnpg, const float* __restrict__ lnpb,
    const float* __restrict__ Wb,   const float* __restrict__ bb,
    float* __restrict__ out) {
    int c = blockIdx.y;
    int ibase = blockIdx.x * IB;

    extern __shared__ float sm[];
    float* ksh   = sm;                    // [JT][KS]
    float* pbar  = ksh + JT * KS;         // [JT][PS]
    float* qsh   = pbar + JT * PS;        // [IB][ED]
    float* wbs   = qsh + IB * ED;         // [NH][PD]
    float* vfsh  = wbs + NH * PD;         // [NH][33]
    float* delsh = vfsh + NH * 33;        // [JT][4]
    float* bbs   = delsh + JT * 4;        // [NH]
    float* gsm   = bbs + NH;              // [PD]
    float* bsm   = gsm + PD;              // [PD]
    float* facc  = bsm + PD;              // [IB*3]

    int tid = threadIdx.x;
    for (int idx = tid; idx < NH * PD; idx += 256) wbs[idx] = Wb[idx];
    if (tid < NH) bbs[tid] = bb[tid];
    if (tid < PD) { gsm[tid] = lnpg[tid]; bsm[tid] = lnpb[tid]; }
    for (int idx = tid; idx < IB * ED; idx += 256) {
        int ii = idx >> 9, e = idx & (ED - 1);
        qsh[idx] = g_q[((size_t)(c * NN) + ibase + ii) * ED + e];
    }
    if (tid < IB * 3) facc[tid] = 0.f;

    int h = tid >> 3, lane = tid & 7;

    float m_[IB], l_[IB], n0_[IB], n1_[IB], n2_[IB];
#pragma unroll
    for (int ii = 0; ii < IB; ii++) {
        m_[ii] = -1e30f; l_[ii] = 0.f; n0_[ii] = 0.f; n1_[ii] = 0.f; n2_[ii] = 0.f;
    }

    for (int jb = 0; jb < NN; jb += JT) {
        __syncthreads();  // previous tile's compute done before ksh overwrite
        // K tile: [JT][512] -> smem (shared across the IB query rows)
        for (int idx = tid; idx < JT * (ED / 4); idx += 256) {
            int jj = idx >> 7;       // /128 float4 per row
            int e4 = idx & 127;
            float4 kv = *(const float4*)&g_k[((size_t)(c * NN) + jb + jj) * ED + e4 * 4];
            *(float4*)&ksh[jj * KS + e4 * 4] = kv;
        }
        // vf tile
        for (int idx = tid; idx < NH * JT; idx += 256) {
            int hh = idx >> 5, jj = idx & 31;
            vfsh[hh * 33 + jj] = g_vf[(size_t)(c * NH + hh) * NN + jb + jj];
        }

        for (int ii = 0; ii < IB; ii++) {
            int i = ibase + ii;
            __syncthreads();  // ksh ready (ii=0) / previous ii done reading pbar
            // LayerNorm of pair rows [i, jb..jb+JT): 8 threads per row
            {
                int row = tid >> 3, t = tid & 7;
                const float* pr = pair + (((size_t)(c * NN) + i) * NN + (jb + row)) * PD + t * 8;
                float4 a  = *(const float4*)pr;
                float4 bq = *(const float4*)(pr + 4);
                float s  = a.x + a.y + a.z + a.w + bq.x + bq.y + bq.z + bq.w;
                float s2 = a.x * a.x + a.y * a.y + a.z * a.z + a.w * a.w
                         + bq.x * bq.x + bq.y * bq.y + bq.z * bq.z + bq.w * bq.w;
#pragma unroll
                for (int off = 4; off; off >>= 1) {
                    s  += __shfl_down_sync(0xffffffffu, s,  off, 8);
                    s2 += __shfl_down_sync(0xffffffffu, s2, off, 8);
                }
                s  = __shfl_sync(0xffffffffu, s,  0, 8);
                s2 = __shfl_sync(0xffffffffu, s2, 0, 8);
                float mu   = s * (1.f / PD);
                float var  = s2 * (1.f / PD) - mu * mu;
                float rstd = rsqrtf(var + 1e-5f);
                float* pb = pbar + row * PS + t * 8;
                int e0 = t * 8;
                pb[0] = (a.x  - mu) * rstd * gsm[e0 + 0] + bsm[e0 + 0];
                pb[1] = (a.y  - mu) * rstd * gsm[e0 + 1] + bsm[e0 + 1];
                pb[2] = (a.z  - mu) * rstd * gsm[e0 + 2] + bsm[e0 + 2];
                pb[3] = (a.w  - mu) * rstd * gsm[e0 + 3] + bsm[e0 + 3];
                pb[4] = (bq.x - mu) * rstd * gsm[e0 + 4] + bsm[e0 + 4];
                pb[5] = (bq.y - mu) * rstd * gsm[e0 + 5] + bsm[e0 + 5];
                pb[6] = (bq.z - mu) * rstd * gsm[e0 + 6] + bsm[e0 + 6];
                pb[7] = (bq.w - mu) * rstd * gsm[e0 + 7] + bsm[e0 + 7];
            }
            // delta_pos tile rows
            for (int idx = tid; idx < JT * 3; idx += 256) {
                int jj = idx / 3, r = idx - jj * 3;
                delsh[jj * 4 + r] = delta[(((size_t)(c * NN) + i) * NN + (jb + jj)) * 3 + r];
            }
            __syncthreads();

            // per-(head, j-lane) compute
            const float* qp = qsh + ii * ED + h * HD;
            float4 q0 = *(const float4*)(qp + 0);
            float4 q1 = *(const float4*)(qp + 4);
            float4 q2 = *(const float4*)(qp + 8);
            float4 q3 = *(const float4*)(qp + 12);
            const float* wb = wbs + h * PD;
            float bbh = bbs[h];
#pragma unroll
            for (int jj = lane; jj < JT; jj += 8) {
                const float* pb = pbar + jj * PS;
                float bias = bbh;
#pragma unroll
                for (int p = 0; p < PD; p += 4) {
                    float4 pv = *(const float4*)&pb[p];
                    float4 wv = *(const float4*)&wb[p];
                    bias += pv.x * wv.x + pv.y * wv.y + pv.z * wv.z + pv.w * wv.w;
                }
                const float* kr = ksh + jj * KS + h * HD;
                float4 k0 = *(const float4*)(kr + 0);
                float4 k1 = *(const float4*)(kr + 4);
                float4 k2 = *(const float4*)(kr + 8);
                float4 k3 = *(const float4*)(kr + 12);
                float attn = q0.x * k0.x + q0.y * k0.y + q0.z * k0.z + q0.w * k0.w
                           + q1.x * k1.x + q1.y * k1.y + q1.z * k1.z + q1.w * k1.w
                           + q2.x * k2.x + q2.y * k2.y + q2.z * k2.z + q2.w * k2.w
                           + q3.x * k3.x + q3.y * k3.y + q3.z * k3.z + q3.w * k3.w;
                float z = attn + bias;
                float vfv = vfsh[h * 33 + jj];
                float d0 = delsh[jj * 4 + 0];
                float d1 = delsh[jj * 4 + 1];
                float d2 = delsh[jj * 4 + 2];
                // online softmax accumulation
                float mo = m_[ii];
                float mn = fmaxf(mo, z);
                float sc = __expf(mo - mn);
                float w  = __expf(z - mn);
                float wv2 = w * vfv;
                l_[ii]  = l_[ii]  * sc + w;
                n0_[ii] = n0_[ii] * sc + wv2 * d0;
                n1_[ii] = n1_[ii] * sc + wv2 * d1;
                n2_[ii] = n2_[ii] * sc + wv2 * d2;
                m_[ii] = mn;
            }
        }
    }

    // merge the 8 j-lanes of each head (associative softmax merge)
#pragma unroll
    for (int ii = 0; ii < IB; ii++) {
        float mm = m_[ii], ll = l_[ii], a0 = n0_[ii], a1 = n1_[ii], a2 = n2_[ii];
#pragma unroll
        for (int off = 4; off; off >>= 1) {
            float mo = __shfl_down_sync(0xffffffffu, mm, off, 8);
            float lo = __shfl_down_sync(0xffffffffu, ll, off, 8);
            float b0 = __shfl_down_sync(0xffffffffu, a0, off, 8);
            float b1 = __shfl_down_sync(0xffffffffu, a1, off, 8);
            float b2 = __shfl_down_sync(0xffffffffu, a2, off, 8);
            float M  = fmaxf(mm, mo);
            float sA = __expf(mm - M);
            float sB = __expf(mo - M);
            ll = ll * sA + lo * sB;
            a0 = a0 * sA + b0 * sB;
            a1 = a1 * sA + b1 * sB;
            a2 = a2 * sA + b2 * sB;
            mm = M;
        }
        if (lane == 0) {
            float inv = 1.f / ll;
            atomicAdd(&facc[ii * 3 + 0], a0 * inv);
            atomicAdd(&facc[ii * 3 + 1], a1 * inv);
            atomicAdd(&facc[ii * 3 + 2], a2 * inv);
        }
    }
    __syncthreads();
    if (tid < IB * 3) {
        int ii = tid / 3, r = tid - ii * 3;
        out[((size_t)(c * NN) + ibase + ii) * 3 + r] = facc[tid];
    }
}

// ---------------------------------------------------------------------------
// Host launch
// ---------------------------------------------------------------------------
static const int ATTN_SMEM_BYTES =
    (JT * KS + JT * PS + IB * ED + NH * PD + NH * 33 + JT * 4 + NH + PD + PD + IB * 3) * 4;

extern "C" void kernel_launch(void* const* d_in, const int* in_sizes, int n_in,
                              void* d_out, int out_size) {
    const float* query = (const float*)d_in[0];
    const float* pair  = (const float*)d_in[1];
    const float* delta = (const float*)d_in[2];
    const float* lnqg  = (const float*)d_in[3];
    const float* lnqb  = (const float*)d_in[4];
    const float* lnpg  = (const float*)d_in[5];
    const float* lnpb  = (const float*)d_in[6];
    const float* Wq    = (const float*)d_in[7];
    const float* Wk    = (const float*)d_in[8];
    const float* Wv    = (const float*)d_in[9];
    const float* Wb    = (const float*)d_in[10];
    const float* bb    = (const float*)d_in[11];
    const float* Wf    = (const float*)d_in[12];
    float* out = (float*)d_out;

    cudaFuncSetAttribute(attn_force_kernel,
                         cudaFuncAttributeMaxDynamicSharedMemorySize, ATTN_SMEM_BYTES);

    ln_q_kernel<<<NC * NN, 128>>>(query, lnqg, lnqb);

    dim3 gg(ED / 64, (NC * NN) / 64, 3);
    qkv_gemm<<<gg, 256>>>(Wq, Wk, Wv);

    vf_kernel<<<(NC * NN * NH) / 256, 256>>>(Wf);

    attn_force_kernel<<<dim3(NN / IB, NC), 256, ATTN_SMEM_BYTES>>>(
        pair, delta, lnpg, lnpb, Wb, bb, out);
}

// round 2
// speedup vs baseline: 1.4639x; 1.4639x over previous
#include <cuda_runtime.h>
#include <cuda_bf16.h>
#include <cstring>

// Problem constants
#define NC 4
#define NN 512
#define ED 512
#define PD 64
#define NH 32
#define HD 16

// f32x2 packed-math helpers (sm_100+)
#define FMA2(acc, a, b) asm("fma.rn.f32x2 %0, %1, %2, %0;" : "+l"(acc) : "l"(a), "l"(b))
#define MUL2(d, a, b)   asm("mul.rn.f32x2 %0, %1, %2;" : "=l"(d) : "l"(a), "l"(b))
#define PACK2(d, x)     asm("mov.b64 %0, {%1, %1};" : "=l"(d) : "f"(x))
#define UNPACK2(lo, hi, v) asm("mov.b64 {%0, %1}, %2;" : "=f"(lo), "=f"(hi) : "l"(v))

// Scratch (static device arrays; no allocations allowed)
__device__ float g_xq[NC * NN * ED];
__device__ float g_q [NC * NN * ED];
__device__ float g_k [NC * NN * ED];
__device__ float g_v [NC * NN * ED];
__device__ float g_vf[NC * NN * NH];                 // layout [c, j, h]
__device__ float g_bias[(size_t)NC * NN * NN * NH];  // layout [c, i, j, h]  (128 MB)

// ---------------------------------------------------------------------------
// Kernel A: LayerNorm(query) -> g_xq.  One block per row.
// ---------------------------------------------------------------------------
__global__ void ln_q_kernel(const float* __restrict__ x,
                            const float* __restrict__ g,
                            const float* __restrict__ b) {
    int row = blockIdx.x;
    const float* xr = x + (size_t)row * ED;
    float* o = g_xq + (size_t)row * ED;
    int tid = threadIdx.x;  // 128 threads
    float v[4];
    float s = 0.f, s2 = 0.f;
#pragma unroll
    for (int t = 0; t < 4; t++) {
        float vv = xr[tid + t * 128];
        v[t] = vv; s += vv; s2 += vv * vv;
    }
#pragma unroll
    for (int off = 16; off; off >>= 1) {
        s  += __shfl_down_sync(0xffffffffu, s,  off);
        s2 += __shfl_down_sync(0xffffffffu, s2, off);
    }
    __shared__ float sh[8];
    if ((tid & 31) == 0) { sh[tid >> 5] = s; sh[4 + (tid >> 5)] = s2; }
    __syncthreads();
    float S  = sh[0] + sh[1] + sh[2] + sh[3];
    float S2 = sh[4] + sh[5] + sh[6] + sh[7];
    float mu   = S * (1.f / ED);
    float var  = S2 * (1.f / ED) - mu * mu;
    float rstd = rsqrtf(var + 1e-5f);
#pragma unroll
    for (int t = 0; t < 4; t++) {
        int e = tid + t * 128;
        o[e] = (v[t] - mu) * rstd * g[e] + b[e];
    }
}

// ---------------------------------------------------------------------------
// Kernel B: QKV projection GEMM (f32x2 packed).  O[m][o] = sum_e xq[m][e]*W[o][e]
// ---------------------------------------------------------------------------
__global__ void __launch_bounds__(256) qkv_gemm(
    const float* __restrict__ Wq, const float* __restrict__ Wk,
    const float* __restrict__ Wv) {
    const float* W; float* O; float scale = 1.f;
    if (blockIdx.z == 0)      { W = Wq; O = g_q; scale = 0.25f; }
    else if (blockIdx.z == 1) { W = Wk; O = g_k; }
    else                      { W = Wv; O = g_v; }
    const float* A = g_xq;

    __shared__ float As[16][68];
    __shared__ float Bs[16][68];
    int tid = threadIdx.x;
    int tx = tid & 15, ty = tid >> 4;
    int m0 = blockIdx.y * 64, n0 = blockIdx.x * 64;
    unsigned long long acc[4][2];
#pragma unroll
    for (int i = 0; i < 4; i++) { acc[i][0] = 0ull; acc[i][1] = 0ull; }
    int lr = tid >> 2;
    int lk = (tid & 3) * 4;

    for (int k0 = 0; k0 < ED; k0 += 16) {
        float4 av = *(const float4*)&A[(size_t)(m0 + lr) * ED + k0 + lk];
        float4 bv = *(const float4*)&W[(size_t)(n0 + lr) * ED + k0 + lk];
        As[lk + 0][lr] = av.x; As[lk + 1][lr] = av.y;
        As[lk + 2][lr] = av.z; As[lk + 3][lr] = av.w;
        Bs[lk + 0][lr] = bv.x; Bs[lk + 1][lr] = bv.y;
        Bs[lk + 2][lr] = bv.z; Bs[lk + 3][lr] = bv.w;
        __syncthreads();
#pragma unroll
        for (int kk = 0; kk < 16; kk++) {
            float4 ar = *(const float4*)&As[kk][ty * 4];
            ulonglong2 br = *(const ulonglong2*)&Bs[kk][tx * 4];
            unsigned long long a0, a1, a2, a3;
            PACK2(a0, ar.x); PACK2(a1, ar.y); PACK2(a2, ar.z); PACK2(a3, ar.w);
            FMA2(acc[0][0], a0, br.x); FMA2(acc[0][1], a0, br.y);
            FMA2(acc[1][0], a1, br.x); FMA2(acc[1][1], a1, br.y);
            FMA2(acc[2][0], a2, br.x); FMA2(acc[2][1], a2, br.y);
            FMA2(acc[3][0], a3, br.x); FMA2(acc[3][1], a3, br.y);
        }
        __syncthreads();
    }
#pragma unroll
    for (int i = 0; i < 4; i++) {
        float4 o; float lo, hi;
        UNPACK2(lo, hi, acc[i][0]); o.x = lo * scale; o.y = hi * scale;
        UNPACK2(lo, hi, acc[i][1]); o.z = lo * scale; o.w = hi * scale;
        *(float4*)&O[(size_t)(m0 + ty * 4 + i) * ED + n0 + tx * 4] = o;
    }
}

// ---------------------------------------------------------------------------
// Kernel C: vf[c,j,h] = sum_d v[c,j,h*16+d] * Wf[h*16+d]
// ---------------------------------------------------------------------------
__global__ void vf_kernel(const float* __restrict__ Wf) {
    int idx = blockIdx.x * blockDim.x + threadIdx.x;  // NC*NN*NH
    int h = idx & 31;
    int cj = idx >> 5;
    const float* vr = g_v + (size_t)cj * ED + h * HD;
    const float* wf = Wf + h * HD;
    float s = 0.f;
#pragma unroll
    for (int d = 0; d < HD; d++) s += vr[d] * wf[d];
    g_vf[(size_t)cj * NH + h] = s;
}

// ---------------------------------------------------------------------------
// Kernel E: pair-LN + bias GEMM.
// rows = flattened (c,i,j), 128 rows/block.  bias[row][h] = LN(pair[row])·Wb[h] + bb[h]
// Inner: 4 rows x 4 heads per thread, f32x2 packed over p-parity.
// ---------------------------------------------------------------------------
#define BR 128
__global__ void __launch_bounds__(256) bias_kernel(
    const float* __restrict__ pair, const float* __restrict__ lnpg,
    const float* __restrict__ lnpb, const float* __restrict__ Wb,
    const float* __restrict__ bb) {
    __shared__ float pt[BR * 68];          // LN'd pair tile, padded
    __shared__ float wbt2[32 * 32 * 2];    // [p-pair][h][2] : (Wb[h][2pp], Wb[h][2pp+1])
    __shared__ float gs[64], bs[64], bbs[32];
    int tid = threadIdx.x;
    size_t rowbase = (size_t)blockIdx.x * BR;

    // load pair tile (coalesced; rows are contiguous in global)
    const float4* src = (const float4*)(pair + rowbase * PD);
#pragma unroll
    for (int t = 0; t < 8; t++) {
        int idx = tid + t * 256;          // 0..2047 float4
        int row = idx >> 4, f4 = idx & 15;
        float4 v = src[idx];
        *(float4*)&pt[row * 68 + f4 * 4] = v;
    }
    for (int idx = tid; idx < 1024; idx += 256) {
        int pp = idx >> 5, h = idx & 31;
        wbt2[idx * 2 + 0] = Wb[h * PD + 2 * pp];
        wbt2[idx * 2 + 1] = Wb[h * PD + 2 * pp + 1];
    }
    if (tid < 64) { gs[tid] = lnpg[tid]; bs[tid] = lnpb[tid]; }
    if (tid < 32) bbs[tid] = bb[tid];
    __syncthreads();

    // LayerNorm in place: 2 threads per row
    {
        int row = tid >> 1, half = tid & 1;
        float* pr = pt + row * 68 + half * 32;
        float s = 0.f, s2 = 0.f;
        float4 v[8];
#pragma unroll
        for (int t = 0; t < 8; t++) {
            v[t] = *(const float4*)&pr[t * 4];
            s  += v[t].x + v[t].y + v[t].z + v[t].w;
            s2 += v[t].x * v[t].x + v[t].y * v[t].y + v[t].z * v[t].z + v[t].w * v[t].w;
        }
        s  += __shfl_xor_sync(0xffffffffu, s, 1);
        s2 += __shfl_xor_sync(0xffffffffu, s2, 1);
        float mu   = s * (1.f / PD);
        float var  = s2 * (1.f / PD) - mu * mu;
        float rstd = rsqrtf(var + 1e-5f);
        int p0 = half * 32;
#pragma unroll
        for (int t = 0; t < 8; t++) {
            float4 o;
            o.x = (v[t].x - mu) * rstd * gs[p0 + t * 4 + 0] + bs[p0 + t * 4 + 0];
            o.y = (v[t].y - mu) * rstd * gs[p0 + t * 4 + 1] + bs[p0 + t * 4 + 1];
            o.z = (v[t].z - mu) * rstd * gs[p0 + t * 4 + 2] + bs[p0 + t * 4 + 2];
            o.w = (v[t].w - mu) * rstd * gs[p0 + t * 4 + 3] + bs[p0 + t * 4 + 3];
            *(float4*)&pr[t * 4] = o;
        }
    }
    __syncthreads();

    // GEMM: thread = (rg, hg); rows {rg, rg+32, rg+64, rg+96}, heads hg*4..+3
    int rg = tid >> 3, hg = tid & 7;
    unsigned long long acc[4][4];
#pragma unroll
    for (int r = 0; r < 4; r++)
#pragma unroll
        for (int hh = 0; hh < 4; hh++) acc[r][hh] = 0ull;

#pragma unroll
    for (int ck = 0; ck < 16; ck++) {
        int p0 = ck * 4;
        ulonglong2 pv[4];
#pragma unroll
        for (int r = 0; r < 4; r++)
            pv[r] = *(const ulonglong2*)&pt[(rg + 32 * r) * 68 + p0];
        // wv for p-pairs pq=0,1:  float offset (pp*32 + h)*2
        ulonglong2 w0a = *(const ulonglong2*)&wbt2[(ck * 2 + 0) * 64 + hg * 8];
        ulonglong2 w0b = *(const ulonglong2*)&wbt2[(ck * 2 + 0) * 64 + hg * 8 + 4];
        ulonglong2 w1a = *(const ulonglong2*)&wbt2[(ck * 2 + 1) * 64 + hg * 8];
        ulonglong2 w1b = *(const ulonglong2*)&wbt2[(ck * 2 + 1) * 64 + hg * 8 + 4];
#pragma unroll
        for (int r = 0; r < 4; r++) {
            FMA2(acc[r][0], pv[r].x, w0a.x);
            FMA2(acc[r][1], pv[r].x, w0a.y);
            FMA2(acc[r][2], pv[r].x, w0b.x);
            FMA2(acc[r][3], pv[r].x, w0b.y);
            FMA2(acc[r][0], pv[r].y, w1a.x);
            FMA2(acc[r][1], pv[r].y, w1a.y);
            FMA2(acc[r][2], pv[r].y, w1b.x);
            FMA2(acc[r][3], pv[r].y, w1b.y);
        }
    }

    // epilogue: reduce parity halves, add bb, coalesced-ish STG.128
#pragma unroll
    for (int r = 0; r < 4; r++) {
        float4 o; float lo, hi;
        UNPACK2(lo, hi, acc[r][0]); o.x = lo + hi + bbs[hg * 4 + 0];
        UNPACK2(lo, hi, acc[r][1]); o.y = lo + hi + bbs[hg * 4 + 1];
        UNPACK2(lo, hi, acc[r][2]); o.z = lo + hi + bbs[hg * 4 + 2];
        UNPACK2(lo, hi, acc[r][3]); o.w = lo + hi + bbs[hg * 4 + 3];
        *(float4*)&g_bias[(rowbase + rg + 32 * r) * NH + hg * 4] = o;
    }
}

// ---------------------------------------------------------------------------
// Kernel F: streaming attention + force.  Block = (4 i-rows, c), 128 threads.
// lane = head h, warp w handles j == w (mod 4).  No smem in main loop.
// Plain exp (logits bounded ~|8|, fp32 safe); merge across warps at end.
// ---------------------------------------------------------------------------
__global__ void __launch_bounds__(128) attn_kernel(
    const float* __restrict__ delta, float* __restrict__ out) {
    int c = blockIdx.y;
    int ibase = blockIdx.x * 4;
    int tid = threadIdx.x;
    int w = tid >> 5, h = tid & 31;

    // q for 4 i-rows, this head: 16 floats = 4x ulonglong2 each (64 regs)
    ulonglong2 q[4][4];
#pragma unroll
    for (int ii = 0; ii < 4; ii++) {
        const float* qp = g_q + ((size_t)(c * NN) + ibase + ii) * ED + h * HD;
#pragma unroll
        for (int t = 0; t < 4; t++)
            q[ii][t] = *(const ulonglong2*)(qp + t * 4);
    }

    float l[4]  = {0.f, 0.f, 0.f, 0.f};
    float n0[4] = {0.f, 0.f, 0.f, 0.f};
    float n1[4] = {0.f, 0.f, 0.f, 0.f};
    float n2[4] = {0.f, 0.f, 0.f, 0.f};

    const size_t cb = (size_t)(c * NN) + ibase;     // row index of i=ibase
#pragma unroll 2
    for (int j = w; j < NN; j += 4) {
        const float* kp = g_k + ((size_t)(c * NN) + j) * ED + h * HD;
        ulonglong2 k0 = *(const ulonglong2*)(kp + 0);
        ulonglong2 k1 = *(const ulonglong2*)(kp + 4);
        ulonglong2 k2 = *(const ulonglong2*)(kp + 8);
        ulonglong2 k3 = *(const ulonglong2*)(kp + 12);
        float vfv = g_vf[((size_t)(c * NN) + j) * NH + h];
        const float* dp = delta + (cb * NN + j) * 3;          // ii stride = NN*3
        const float* bp = g_bias + (cb * NN + j) * NH + h;    // ii stride = NN*NH
#pragma unroll
        for (int ii = 0; ii < 4; ii++) {
            unsigned long long a;
            MUL2(a, q[ii][0].x, k0.x);
            FMA2(a, q[ii][0].y, k0.y);
            FMA2(a, q[ii][1].x, k1.x);
            FMA2(a, q[ii][1].y, k1.y);
            FMA2(a, q[ii][2].x, k2.x);
            FMA2(a, q[ii][2].y, k2.y);
            FMA2(a, q[ii][3].x, k3.x);
            FMA2(a, q[ii][3].y, k3.y);
            float lo, hi; UNPACK2(lo, hi, a);
            float z = lo + hi + bp[(size_t)ii * (NN * NH)];
            float we = __expf(z);
            float wv = we * vfv;
            float d0 = dp[ii * (NN * 3) + 0];
            float d1 = dp[ii * (NN * 3) + 1];
            float d2 = dp[ii * (NN * 3) + 2];
            l[ii]  += we;
            n0[ii] += wv * d0;
            n1[ii] += wv * d1;
            n2[ii] += wv * d2;
        }
    }

    __shared__ float ms[4][4][32][4];
#pragma unroll
    for (int ii = 0; ii < 4; ii++)
        *(float4*)&ms[w][ii][h][0] = make_float4(l[ii], n0[ii], n1[ii], n2[ii]);
    __syncthreads();

    // warp w merges i-row ii = w
    {
        int ii = w;
        float4 a0 = *(const float4*)&ms[0][ii][h][0];
        float4 a1 = *(const float4*)&ms[1][ii][h][0];
        float4 a2 = *(const float4*)&ms[2][ii][h][0];
        float4 a3 = *(const float4*)&ms[3][ii][h][0];
        float L  = a0.x + a1.x + a2.x + a3.x;
        float inv = 1.f / L;
        float F0 = (a0.y + a1.y + a2.y + a3.y) * inv;
        float F1 = (a0.z + a1.z + a2.z + a3.z) * inv;
        float F2 = (a0.w + a1.w + a2.w + a3.w) * inv;
#pragma unroll
        for (int off = 16; off; off >>= 1) {
            F0 += __shfl_down_sync(0xffffffffu, F0, off);
            F1 += __shfl_down_sync(0xffffffffu, F1, off);
            F2 += __shfl_down_sync(0xffffffffu, F2, off);
        }
        if (h == 0) {
            float* op = out + ((size_t)(c * NN) + ibase + ii) * 3;
            op[0] = F0; op[1] = F1; op[2] = F2;
        }
    }
}

// ---------------------------------------------------------------------------
// Host launch
// ---------------------------------------------------------------------------
extern "C" void kernel_launch(void* const* d_in, const int* in_sizes, int n_in,
                              void* d_out, int out_size) {
    const float* query = (const float*)d_in[0];
    const float* pair  = (const float*)d_in[1];
    const float* delta = (const float*)d_in[2];
    const float* lnqg  = (const float*)d_in[3];
    const float* lnqb  = (const float*)d_in[4];
    const float* lnpg  = (const float*)d_in[5];
    const float* lnpb  = (const float*)d_in[6];
    const float* Wq    = (const float*)d_in[7];
    const float* Wk    = (const float*)d_in[8];
    const float* Wv    = (const float*)d_in[9];
    const float* Wb    = (const float*)d_in[10];
    const float* bb    = (const float*)d_in[11];
    const float* Wf    = (const float*)d_in[12];
    float* out = (float*)d_out;

    ln_q_kernel<<<NC * NN, 128>>>(query, lnqg, lnqb);

    dim3 gg(ED / 64, (NC * NN) / 64, 3);
    qkv_gemm<<<gg, 256>>>(Wq, Wk, Wv);

    vf_kernel<<<(NC * NN * NH) / 256, 256>>>(Wf);

    bias_kernel<<<(NC * NN * NN) / BR, 256>>>(pair, lnpg, lnpb, Wb, bb);

    attn_kernel<<<dim3(NN / 4, NC), 128>>>(delta, out);
}

// round 4
// speedup vs baseline: 1.8276x; 1.2484x over previous
#include <cuda_runtime.h>
#include <cuda_bf16.h>

// Problem constants
#define NC 4
#define NN 512
#define ED 512
#define PD 64
#define NH 32
#define HD 16

// f32x2 packed-math helpers (sm_100+)
#define FMA2(acc, a, b) asm("fma.rn.f32x2 %0, %1, %2, %0;" : "+l"(acc) : "l"(a), "l"(b))
#define MUL2(d, a, b)   asm("mul.rn.f32x2 %0, %1, %2;" : "=l"(d) : "l"(a), "l"(b))
#define PACK2(d, x)     asm("mov.b64 %0, {%1, %1};" : "=l"(d) : "f"(x))
#define UNPACK2(lo, hi, v) asm("mov.b64 {%0, %1}, %2;" : "=f"(lo), "=f"(hi) : "l"(v))

#define CVT_TF32(u, f) asm("cvt.rna.tf32.f32 %0, %1;" : "=r"(u) : "f"(f))

__device__ __forceinline__ void mma_tf32(float& d0, float& d1, float& d2, float& d3,
                                         unsigned a0, unsigned a1, unsigned a2, unsigned a3,
                                         unsigned b0, unsigned b1) {
    asm volatile("mma.sync.aligned.m16n8k8.row.col.f32.tf32.tf32.f32 "
                 "{%0,%1,%2,%3}, {%4,%5,%6,%7}, {%8,%9}, {%0,%1,%2,%3};"
                 : "+f"(d0), "+f"(d1), "+f"(d2), "+f"(d3)
                 : "r"(a0), "r"(a1), "r"(a2), "r"(a3), "r"(b0), "r"(b1));
}

// Scratch (static device arrays; no allocations allowed)
__device__ float g_xq[NC * NN * ED];
__device__ float g_q [NC * NN * ED];
__device__ float g_k [NC * NN * ED];
__device__ float g_v [NC * NN * ED];
__device__ float g_vf[NC * NN * NH];                 // [c, j, h]
__device__ float g_bias[(size_t)NC * NN * NN * NH];  // [c, i, j, h]

// ---------------------------------------------------------------------------
// Kernel A: LayerNorm(query) -> g_xq.
// ---------------------------------------------------------------------------
__global__ void ln_q_kernel(const float* __restrict__ x,
                            const float* __restrict__ g,
                            const float* __restrict__ b) {
    int row = blockIdx.x;
    const float* xr = x + (size_t)row * ED;
    float* o = g_xq + (size_t)row * ED;
    int tid = threadIdx.x;  // 128
    float v[4];
    float s = 0.f, s2 = 0.f;
#pragma unroll
    for (int t = 0; t < 4; t++) {
        float vv = xr[tid + t * 128];
        v[t] = vv; s += vv; s2 += vv * vv;
    }
#pragma unroll
    for (int off = 16; off; off >>= 1) {
        s  += __shfl_down_sync(0xffffffffu, s,  off);
        s2 += __shfl_down_sync(0xffffffffu, s2, off);
    }
    __shared__ float sh[8];
    if ((tid & 31) == 0) { sh[tid >> 5] = s; sh[4 + (tid >> 5)] = s2; }
    __syncthreads();
    float S  = sh[0] + sh[1] + sh[2] + sh[3];
    float S2 = sh[4] + sh[5] + sh[6] + sh[7];
    float mu   = S * (1.f / ED);
    float var  = S2 * (1.f / ED) - mu * mu;
    float rstd = rsqrtf(var + 1e-5f);
#pragma unroll
    for (int t = 0; t < 4; t++) {
        int e = tid + t * 128;
        o[e] = (v[t] - mu) * rstd * g[e] + b[e];
    }
}

// ---------------------------------------------------------------------------
// Kernel B: QKV projection GEMM (f32x2 packed).
// ---------------------------------------------------------------------------
__global__ void __launch_bounds__(256) qkv_gemm(
    const float* __restrict__ Wq, const float* __restrict__ Wk,
    const float* __restrict__ Wv) {
    const float* W; float* O; float scale = 1.f;
    if (blockIdx.z == 0)      { W = Wq; O = g_q; scale = 0.25f; }
    else if (blockIdx.z == 1) { W = Wk; O = g_k; }
    else                      { W = Wv; O = g_v; }
    const float* A = g_xq;

    __shared__ float As[16][68];
    __shared__ float Bs[16][68];
    int tid = threadIdx.x;
    int tx = tid & 15, ty = tid >> 4;
    int m0 = blockIdx.y * 64, n0 = blockIdx.x * 64;
    unsigned long long acc[4][2];
#pragma unroll
    for (int i = 0; i < 4; i++) { acc[i][0] = 0ull; acc[i][1] = 0ull; }
    int lr = tid >> 2;
    int lk = (tid & 3) * 4;

    for (int k0 = 0; k0 < ED; k0 += 16) {
        float4 av = *(const float4*)&A[(size_t)(m0 + lr) * ED + k0 + lk];
        float4 bv = *(const float4*)&W[(size_t)(n0 + lr) * ED + k0 + lk];
        As[lk + 0][lr] = av.x; As[lk + 1][lr] = av.y;
        As[lk + 2][lr] = av.z; As[lk + 3][lr] = av.w;
        Bs[lk + 0][lr] = bv.x; Bs[lk + 1][lr] = bv.y;
        Bs[lk + 2][lr] = bv.z; Bs[lk + 3][lr] = bv.w;
        __syncthreads();
#pragma unroll
        for (int kk = 0; kk < 16; kk++) {
            float4 ar = *(const float4*)&As[kk][ty * 4];
            ulonglong2 br = *(const ulonglong2*)&Bs[kk][tx * 4];
            unsigned long long a0, a1, a2, a3;
            PACK2(a0, ar.x); PACK2(a1, ar.y); PACK2(a2, ar.z); PACK2(a3, ar.w);
            FMA2(acc[0][0], a0, br.x); FMA2(acc[0][1], a0, br.y);
            FMA2(acc[1][0], a1, br.x); FMA2(acc[1][1], a1, br.y);
            FMA2(acc[2][0], a2, br.x); FMA2(acc[2][1], a2, br.y);
            FMA2(acc[3][0], a3, br.x); FMA2(acc[3][1], a3, br.y);
        }
        __syncthreads();
    }
#pragma unroll
    for (int i = 0; i < 4; i++) {
        float4 o; float lo, hi;
        UNPACK2(lo, hi, acc[i][0]); o.x = lo * scale; o.y = hi * scale;
        UNPACK2(lo, hi, acc[i][1]); o.z = lo * scale; o.w = hi * scale;
        *(float4*)&O[(size_t)(m0 + ty * 4 + i) * ED + n0 + tx * 4] = o;
    }
}

// ---------------------------------------------------------------------------
// Kernel C: vf[c,j,h] = sum_d v[c,j,h*16+d] * Wf[h*16+d]
// ---------------------------------------------------------------------------
__global__ void vf_kernel(const float* __restrict__ Wf) {
    int idx = blockIdx.x * blockDim.x + threadIdx.x;
    int h = idx & 31;
    int cj = idx >> 5;
    const float* vr = g_v + (size_t)cj * ED + h * HD;
    const float* wf = Wf + h * HD;
    float s = 0.f;
#pragma unroll
    for (int d = 0; d < HD; d++) s += vr[d] * wf[d];
    g_vf[(size_t)cj * NH + h] = s;
}

// ---------------------------------------------------------------------------
// Kernel E: pair-LN + bias GEMM on tensor cores (tf32 3-mma split).
// 128 rows/block, 256 threads (8 warps, warp = m16 strip).
// D[m][h] = LN(pair[m])·Wb[h] + bb[h]
// ---------------------------------------------------------------------------
#define BM 128
__global__ void __launch_bounds__(256) bias_kernel(
    const float* __restrict__ pair, const float* __restrict__ lnpg,
    const float* __restrict__ lnpb, const float* __restrict__ Wb,
    const float* __restrict__ bb) {
    __shared__ float pt[BM * 68];     // LN'd pair tile (fp32)
    __shared__ float wbs[64 * 36];    // wbs[k*36+n] = Wb[n][k]  (fp32)
    __shared__ float gs[64], bs[64], bbs[32];
    int tid = threadIdx.x;
    size_t rowbase = (size_t)blockIdx.x * BM;

    // load pair tile (coalesced)
    const float4* src = (const float4*)(pair + rowbase * PD);
#pragma unroll
    for (int t = 0; t < 8; t++) {
        int idx = tid + t * 256;
        int row = idx >> 4, f4 = idx & 15;
        float4 v = src[idx];
        *(float4*)&pt[row * 68 + f4 * 4] = v;
    }
    // Wb transposed into smem
    for (int idx = tid; idx < 2048; idx += 256) {
        int n = idx >> 6, k = idx & 63;
        wbs[k * 36 + n] = Wb[idx];
    }
    if (tid < 64) { gs[tid] = lnpg[tid]; bs[tid] = lnpb[tid]; }
    if (tid < 32) bbs[tid] = bb[tid];
    __syncthreads();

    // LayerNorm in place: 2 threads per row
    {
        int row = tid >> 1, half = tid & 1;
        float* pr = pt + row * 68 + half * 32;
        float s = 0.f, s2 = 0.f;
        float4 v[8];
#pragma unroll
        for (int t = 0; t < 8; t++) {
            v[t] = *(const float4*)&pr[t * 4];
            s  += v[t].x + v[t].y + v[t].z + v[t].w;
            s2 += v[t].x * v[t].x + v[t].y * v[t].y + v[t].z * v[t].z + v[t].w * v[t].w;
        }
        s  += __shfl_xor_sync(0xffffffffu, s, 1);
        s2 += __shfl_xor_sync(0xffffffffu, s2, 1);
        float mu   = s * (1.f / PD);
        float var  = s2 * (1.f / PD) - mu * mu;
        float rstd = rsqrtf(var + 1e-5f);
        int p0 = half * 32;
#pragma unroll
        for (int t = 0; t < 8; t++) {
            float4 o;
            o.x = (v[t].x - mu) * rstd * gs[p0 + t * 4 + 0] + bs[p0 + t * 4 + 0];
            o.y = (v[t].y - mu) * rstd * gs[p0 + t * 4 + 1] + bs[p0 + t * 4 + 1];
            o.z = (v[t].z - mu) * rstd * gs[p0 + t * 4 + 2] + bs[p0 + t * 4 + 2];
            o.w = (v[t].w - mu) * rstd * gs[p0 + t * 4 + 3] + bs[p0 + t * 4 + 3];
            *(float4*)&pr[t * 4] = o;
        }
    }
    __syncthreads();

    // Tensor-core GEMM: warp w handles rows [w*16, w*16+16), all 32 heads.
    int w = tid >> 5, lane = tid & 31;
    int lr = lane >> 2, lc = lane & 3;   // groupID, threadID_in_group
    int arow0 = w * 16 + lr;

    // accumulators: 4 n-chunks x 4 regs, init with bias bb
    float d[4][4];
#pragma unroll
    for (int nc = 0; nc < 4; nc++) {
        float b0 = bbs[nc * 8 + 2 * lc], b1 = bbs[nc * 8 + 2 * lc + 1];
        d[nc][0] = b0; d[nc][1] = b1; d[nc][2] = b0; d[nc][3] = b1;
    }

#pragma unroll
    for (int kc = 0; kc < 8; kc++) {
        // A fragment (fp32) + hi/lo tf32 split
        float af[4];
        af[0] = pt[arow0 * 68 + kc * 8 + lc];
        af[1] = pt[(arow0 + 8) * 68 + kc * 8 + lc];
        af[2] = pt[arow0 * 68 + kc * 8 + lc + 4];
        af[3] = pt[(arow0 + 8) * 68 + kc * 8 + lc + 4];
        unsigned ah[4], al[4];
#pragma unroll
        for (int t = 0; t < 4; t++) {
            CVT_TF32(ah[t], af[t]);
            float res = af[t] - __uint_as_float(ah[t]);
            CVT_TF32(al[t], res);
        }
#pragma unroll
        for (int nc = 0; nc < 4; nc++) {
            float bf0 = wbs[(kc * 8 + lc) * 36 + nc * 8 + lr];
            float bf1 = wbs[(kc * 8 + lc + 4) * 36 + nc * 8 + lr];
            unsigned bh0, bh1, bl0, bl1;
            CVT_TF32(bh0, bf0);
            CVT_TF32(bh1, bf1);
            float r0 = bf0 - __uint_as_float(bh0);
            float r1 = bf1 - __uint_as_float(bh1);
            CVT_TF32(bl0, r0);
            CVT_TF32(bl1, r1);
            mma_tf32(d[nc][0], d[nc][1], d[nc][2], d[nc][3],
                     ah[0], ah[1], ah[2], ah[3], bh0, bh1);
            mma_tf32(d[nc][0], d[nc][1], d[nc][2], d[nc][3],
                     ah[0], ah[1], ah[2], ah[3], bl0, bl1);
            mma_tf32(d[nc][0], d[nc][1], d[nc][2], d[nc][3],
                     al[0], al[1], al[2], al[3], bh0, bh1);
        }
    }

    // epilogue: D fragment -> g_bias rows
    size_t row = rowbase + arow0;
#pragma unroll
    for (int nc = 0; nc < 4; nc++) {
        int col = nc * 8 + 2 * lc;
        *(float2*)&g_bias[row * NH + col]       = make_float2(d[nc][0], d[nc][1]);
        *(float2*)&g_bias[(row + 8) * NH + col] = make_float2(d[nc][2], d[nc][3]);
    }
}

// ---------------------------------------------------------------------------
// Kernel F: streaming attention + force (EXACT round-2 proven version).
// Block = (4 i-rows, c), 128 threads.  lane = head h, warp w covers j mod 4.
// ---------------------------------------------------------------------------
__global__ void __launch_bounds__(128) attn_kernel(
    const float* __restrict__ delta, float* __restrict__ out) {
    int c = blockIdx.y;
    int ibase = blockIdx.x * 4;
    int tid = threadIdx.x;
    int w = tid >> 5, h = tid & 31;

    ulonglong2 q[4][4];
#pragma unroll
    for (int ii = 0; ii < 4; ii++) {
        const float* qp = g_q + ((size_t)(c * NN) + ibase + ii) * ED + h * HD;
#pragma unroll
        for (int t = 0; t < 4; t++)
            q[ii][t] = *(const ulonglong2*)(qp + t * 4);
    }

    float l[4]  = {0.f, 0.f, 0.f, 0.f};
    float n0[4] = {0.f, 0.f, 0.f, 0.f};
    float n1[4] = {0.f, 0.f, 0.f, 0.f};
    float n2[4] = {0.f, 0.f, 0.f, 0.f};

    const size_t cb = (size_t)(c * NN) + ibase;
#pragma unroll 2
    for (int j = w; j < NN; j += 4) {
        const float* kp = g_k + ((size_t)(c * NN) + j) * ED + h * HD;
        ulonglong2 k0 = *(const ulonglong2*)(kp + 0);
        ulonglong2 k1 = *(const ulonglong2*)(kp + 4);
        ulonglong2 k2 = *(const ulonglong2*)(kp + 8);
        ulonglong2 k3 = *(const ulonglong2*)(kp + 12);
        float vfv = g_vf[((size_t)(c * NN) + j) * NH + h];
        const float* dp = delta + (cb * NN + j) * 3;
        const float* bp = g_bias + (cb * NN + j) * NH + h;
#pragma unroll
        for (int ii = 0; ii < 4; ii++) {
            unsigned long long a;
            MUL2(a, q[ii][0].x, k0.x);
            FMA2(a, q[ii][0].y, k0.y);
            FMA2(a, q[ii][1].x, k1.x);
            FMA2(a, q[ii][1].y, k1.y);
            FMA2(a, q[ii][2].x, k2.x);
            FMA2(a, q[ii][2].y, k2.y);
            FMA2(a, q[ii][3].x, k3.x);
            FMA2(a, q[ii][3].y, k3.y);
            float lo, hi; UNPACK2(lo, hi, a);
            float z = lo + hi + bp[(size_t)ii * (NN * NH)];
            float we = __expf(z);
            float wv = we * vfv;
            float d0 = dp[ii * (NN * 3) + 0];
            float d1 = dp[ii * (NN * 3) + 1];
            float d2 = dp[ii * (NN * 3) + 2];
            l[ii]  += we;
            n0[ii] += wv * d0;
            n1[ii] += wv * d1;
            n2[ii] += wv * d2;
        }
    }

    __shared__ float ms[4][4][32][4];
#pragma unroll
    for (int ii = 0; ii < 4; ii++)
        *(float4*)&ms[w][ii][h][0] = make_float4(l[ii], n0[ii], n1[ii], n2[ii]);
    __syncthreads();

    {
        int ii = w;
        float4 a0 = *(const float4*)&ms[0][ii][h][0];
        float4 a1 = *(const float4*)&ms[1][ii][h][0];
        float4 a2 = *(const float4*)&ms[2][ii][h][0];
        float4 a3 = *(const float4*)&ms[3][ii][h][0];
        float L  = a0.x + a1.x + a2.x + a3.x;
        float inv = 1.f / L;
        float F0 = (a0.y + a1.y + a2.y + a3.y) * inv;
        float F1 = (a0.z + a1.z + a2.z + a3.z) * inv;
        float F2 = (a0.w + a1.w + a2.w + a3.w) * inv;
#pragma unroll
        for (int off = 16; off; off >>= 1) {
            F0 += __shfl_down_sync(0xffffffffu, F0, off);
            F1 += __shfl_down_sync(0xffffffffu, F1, off);
            F2 += __shfl_down_sync(0xffffffffu, F2, off);
        }
        if (h == 0) {
            float* op = out + ((size_t)(c * NN) + ibase + ii) * 3;
            op[0] = F0; op[1] = F1; op[2] = F2;
        }
    }
}

// ---------------------------------------------------------------------------
// Host launch
// ---------------------------------------------------------------------------
extern "C" void kernel_launch(void* const* d_in, const int* in_sizes, int n_in,
                              void* d_out, int out_size) {
    const float* query = (const float*)d_in[0];
    const float* pair  = (const float*)d_in[1];
    const float* delta = (const float*)d_in[2];
    const float* lnqg  = (const float*)d_in[3];
    const float* lnqb  = (const float*)d_in[4];
    const float* lnpg  = (const float*)d_in[5];
    const float* lnpb  = (const float*)d_in[6];
    const float* Wq    = (const float*)d_in[7];
    const float* Wk    = (const float*)d_in[8];
    const float* Wv    = (const float*)d_in[9];
    const float* Wb    = (const float*)d_in[10];
    const float* bb    = (const float*)d_in[11];
    const float* Wf    = (const float*)d_in[12];
    float* out = (float*)d_out;

    ln_q_kernel<<<NC * NN, 128>>>(query, lnqg, lnqb);

    dim3 gg(ED / 64, (NC * NN) / 64, 3);
    qkv_gemm<<<gg, 256>>>(Wq, Wk, Wv);

    vf_kernel<<<(NC * NN * NH) / 256, 256>>>(Wf);

    bias_kernel<<<(NC * NN * NN) / BM, 256>>>(pair, lnpg, lnpb, Wb, bb);

    attn_kernel<<<dim3(NN / 4, NC), 128>>>(delta, out);
}

// round 5
// speedup vs baseline: 2.1946x; 1.2009x over previous
#include <cuda_runtime.h>
#include <cuda_bf16.h>

// Problem constants
#define NC 4
#define NN 512
#define ED 512
#define PD 64
#define NH 32
#define HD 16

// f32x2 packed-math helpers (sm_100+)
#define FMA2(acc, a, b) asm("fma.rn.f32x2 %0, %1, %2, %0;" : "+l"(acc) : "l"(a), "l"(b))
#define MUL2(d, a, b)   asm("mul.rn.f32x2 %0, %1, %2;" : "=l"(d) : "l"(a), "l"(b))
#define PACK2(d, x)     asm("mov.b64 %0, {%1, %1};" : "=l"(d) : "f"(x))
#define UNPACK2(lo, hi, v) asm("mov.b64 {%0, %1}, %2;" : "=f"(lo), "=f"(hi) : "l"(v))

#define CVT_TF32(u, f) asm("cvt.rna.tf32.f32 %0, %1;" : "=r"(u) : "f"(f))

__device__ __forceinline__ void mma_tf32(float& d0, float& d1, float& d2, float& d3,
                                         unsigned a0, unsigned a1, unsigned a2, unsigned a3,
                                         unsigned b0, unsigned b1) {
    asm volatile("mma.sync.aligned.m16n8k8.row.col.f32.tf32.tf32.f32 "
                 "{%0,%1,%2,%3}, {%4,%5,%6,%7}, {%8,%9}, {%0,%1,%2,%3};"
                 : "+f"(d0), "+f"(d1), "+f"(d2), "+f"(d3)
                 : "r"(a0), "r"(a1), "r"(a2), "r"(a3), "r"(b0), "r"(b1));
}

// Scratch (static device arrays; no allocations allowed)
__device__ float g_xq[NC * NN * ED];
__device__ float g_q [NC * NN * ED];
__device__ float g_k [NC * NN * ED];
__device__ float g_v [NC * NN * ED];
__device__ float g_vf[NC * NN * NH];                 // [c, j, h]
__device__ float g_bias[(size_t)NC * NN * NN * NH];  // [c, i, j, h]

// ---------------------------------------------------------------------------
// Kernel A: LayerNorm(query) -> g_xq.
// ---------------------------------------------------------------------------
__global__ void ln_q_kernel(const float* __restrict__ x,
                            const float* __restrict__ g,
                            const float* __restrict__ b) {
    int row = blockIdx.x;
    const float* xr = x + (size_t)row * ED;
    float* o = g_xq + (size_t)row * ED;
    int tid = threadIdx.x;  // 128
    float v[4];
    float s = 0.f, s2 = 0.f;
#pragma unroll
    for (int t = 0; t < 4; t++) {
        float vv = xr[tid + t * 128];
        v[t] = vv; s += vv; s2 += vv * vv;
    }
#pragma unroll
    for (int off = 16; off; off >>= 1) {
        s  += __shfl_down_sync(0xffffffffu, s,  off);
        s2 += __shfl_down_sync(0xffffffffu, s2, off);
    }
    __shared__ float sh[8];
    if ((tid & 31) == 0) { sh[tid >> 5] = s; sh[4 + (tid >> 5)] = s2; }
    __syncthreads();
    float S  = sh[0] + sh[1] + sh[2] + sh[3];
    float S2 = sh[4] + sh[5] + sh[6] + sh[7];
    float mu   = S * (1.f / ED);
    float var  = S2 * (1.f / ED) - mu * mu;
    float rstd = rsqrtf(var + 1e-5f);
#pragma unroll
    for (int t = 0; t < 4; t++) {
        int e = tid + t * 128;
        o[e] = (v[t] - mu) * rstd * g[e] + b[e];
    }
}

// ---------------------------------------------------------------------------
// Kernel B: QKV projection GEMM (f32x2 packed).
// ---------------------------------------------------------------------------
__global__ void __launch_bounds__(256) qkv_gemm(
    const float* __restrict__ Wq, const float* __restrict__ Wk,
    const float* __restrict__ Wv) {
    const float* W; float* O; float scale = 1.f;
    if (blockIdx.z == 0)      { W = Wq; O = g_q; scale = 0.25f; }
    else if (blockIdx.z == 1) { W = Wk; O = g_k; }
    else                      { W = Wv; O = g_v; }
    const float* A = g_xq;

    __shared__ float As[16][68];
    __shared__ float Bs[16][68];
    int tid = threadIdx.x;
    int tx = tid & 15, ty = tid >> 4;
    int m0 = blockIdx.y * 64, n0 = blockIdx.x * 64;
    unsigned long long acc[4][2];
#pragma unroll
    for (int i = 0; i < 4; i++) { acc[i][0] = 0ull; acc[i][1] = 0ull; }
    int lr = tid >> 2;
    int lk = (tid & 3) * 4;

    for (int k0 = 0; k0 < ED; k0 += 16) {
        float4 av = *(const float4*)&A[(size_t)(m0 + lr) * ED + k0 + lk];
        float4 bv = *(const float4*)&W[(size_t)(n0 + lr) * ED + k0 + lk];
        As[lk + 0][lr] = av.x; As[lk + 1][lr] = av.y;
        As[lk + 2][lr] = av.z; As[lk + 3][lr] = av.w;
        Bs[lk + 0][lr] = bv.x; Bs[lk + 1][lr] = bv.y;
        Bs[lk + 2][lr] = bv.z; Bs[lk + 3][lr] = bv.w;
        __syncthreads();
#pragma unroll
        for (int kk = 0; kk < 16; kk++) {
            float4 ar = *(const float4*)&As[kk][ty * 4];
            ulonglong2 br = *(const ulonglong2*)&Bs[kk][tx * 4];
            unsigned long long a0, a1, a2, a3;
            PACK2(a0, ar.x); PACK2(a1, ar.y); PACK2(a2, ar.z); PACK2(a3, ar.w);
            FMA2(acc[0][0], a0, br.x); FMA2(acc[0][1], a0, br.y);
            FMA2(acc[1][0], a1, br.x); FMA2(acc[1][1], a1, br.y);
            FMA2(acc[2][0], a2, br.x); FMA2(acc[2][1], a2, br.y);
            FMA2(acc[3][0], a3, br.x); FMA2(acc[3][1], a3, br.y);
        }
        __syncthreads();
    }
#pragma unroll
    for (int i = 0; i < 4; i++) {
        float4 o; float lo, hi;
        UNPACK2(lo, hi, acc[i][0]); o.x = lo * scale; o.y = hi * scale;
        UNPACK2(lo, hi, acc[i][1]); o.z = lo * scale; o.w = hi * scale;
        *(float4*)&O[(size_t)(m0 + ty * 4 + i) * ED + n0 + tx * 4] = o;
    }
}

// ---------------------------------------------------------------------------
// Kernel C: vf[c,j,h] = sum_d v[c,j,h*16+d] * Wf[h*16+d]
// ---------------------------------------------------------------------------
__global__ void vf_kernel(const float* __restrict__ Wf) {
    int idx = blockIdx.x * blockDim.x + threadIdx.x;
    int h = idx & 31;
    int cj = idx >> 5;
    const float* vr = g_v + (size_t)cj * ED + h * HD;
    const float* wf = Wf + h * HD;
    float s = 0.f;
#pragma unroll
    for (int d = 0; d < HD; d++) s += vr[d] * wf[d];
    g_vf[(size_t)cj * NH + h] = s;
}

// ---------------------------------------------------------------------------
// Kernel E: pair-LN + bias GEMM on tensor cores (tf32 3-mma split).
// Wb hi/lo tf32 split precomputed ONCE into smem (uint2 per element).
// Dynamic smem: pt[128*68] f32 | wb2[64*36] uint2 | gs[64] | bs[64] | bbs[32]
// ---------------------------------------------------------------------------
#define BM 128
#define BIAS_SMEM_BYTES (BM * 68 * 4 + 64 * 36 * 8 + 64 * 4 + 64 * 4 + 32 * 4)
__global__ void __launch_bounds__(256) bias_kernel(
    const float* __restrict__ pair, const float* __restrict__ lnpg,
    const float* __restrict__ lnpb, const float* __restrict__ Wb,
    const float* __restrict__ bb) {
    extern __shared__ float smf[];
    float* pt   = smf;                         // [BM*68]
    uint2* wb2  = (uint2*)(pt + BM * 68);      // [64*36]  (hi, lo) of Wb[n][k]
    float* gs   = (float*)(wb2 + 64 * 36);     // [64]
    float* bs   = gs + 64;                     // [64]
    float* bbs  = bs + 64;                     // [32]
    int tid = threadIdx.x;
    size_t rowbase = (size_t)blockIdx.x * BM;

    // load pair tile (coalesced)
    const float4* src = (const float4*)(pair + rowbase * PD);
#pragma unroll
    for (int t = 0; t < 8; t++) {
        int idx = tid + t * 256;
        int row = idx >> 4, f4 = idx & 15;
        float4 v = src[idx];
        *(float4*)&pt[row * 68 + f4 * 4] = v;
    }
    // Wb transposed + pre-split into tf32 hi/lo
    for (int idx = tid; idx < 2048; idx += 256) {
        int n = idx >> 6, k = idx & 63;
        float v = Wb[idx];
        unsigned hi; CVT_TF32(hi, v);
        float r = v - __uint_as_float(hi);
        unsigned lo; CVT_TF32(lo, r);
        wb2[k * 36 + n] = make_uint2(hi, lo);
    }
    if (tid < 64) { gs[tid] = lnpg[tid]; bs[tid] = lnpb[tid]; }
    if (tid < 32) bbs[tid] = bb[tid];
    __syncthreads();

    // LayerNorm in place: 2 threads per row
    {
        int row = tid >> 1, half = tid & 1;
        float* pr = pt + row * 68 + half * 32;
        float s = 0.f, s2 = 0.f;
        float4 v[8];
#pragma unroll
        for (int t = 0; t < 8; t++) {
            v[t] = *(const float4*)&pr[t * 4];
            s  += v[t].x + v[t].y + v[t].z + v[t].w;
            s2 += v[t].x * v[t].x + v[t].y * v[t].y + v[t].z * v[t].z + v[t].w * v[t].w;
        }
        s  += __shfl_xor_sync(0xffffffffu, s, 1);
        s2 += __shfl_xor_sync(0xffffffffu, s2, 1);
        float mu   = s * (1.f / PD);
        float var  = s2 * (1.f / PD) - mu * mu;
        float rstd = rsqrtf(var + 1e-5f);
        int p0 = half * 32;
#pragma unroll
        for (int t = 0; t < 8; t++) {
            float4 o;
            o.x = (v[t].x - mu) * rstd * gs[p0 + t * 4 + 0] + bs[p0 + t * 4 + 0];
            o.y = (v[t].y - mu) * rstd * gs[p0 + t * 4 + 1] + bs[p0 + t * 4 + 1];
            o.z = (v[t].z - mu) * rstd * gs[p0 + t * 4 + 2] + bs[p0 + t * 4 + 2];
            o.w = (v[t].w - mu) * rstd * gs[p0 + t * 4 + 3] + bs[p0 + t * 4 + 3];
            *(float4*)&pr[t * 4] = o;
        }
    }
    __syncthreads();

    // Tensor-core GEMM: warp w handles rows [w*16, w*16+16), all 32 heads.
    int w = tid >> 5, lane = tid & 31;
    int lr = lane >> 2, lc = lane & 3;   // groupID, threadID_in_group
    int arow0 = w * 16 + lr;

    float d[4][4];
#pragma unroll
    for (int nc = 0; nc < 4; nc++) {
        float b0 = bbs[nc * 8 + 2 * lc], b1 = bbs[nc * 8 + 2 * lc + 1];
        d[nc][0] = b0; d[nc][1] = b1; d[nc][2] = b0; d[nc][3] = b1;
    }

#pragma unroll
    for (int kc = 0; kc < 8; kc++) {
        // A fragment (fp32) + hi/lo tf32 split
        float af[4];
        af[0] = pt[arow0 * 68 + kc * 8 + lc];
        af[1] = pt[(arow0 + 8) * 68 + kc * 8 + lc];
        af[2] = pt[arow0 * 68 + kc * 8 + lc + 4];
        af[3] = pt[(arow0 + 8) * 68 + kc * 8 + lc + 4];
        unsigned ah[4], al[4];
#pragma unroll
        for (int t = 0; t < 4; t++) {
            CVT_TF32(ah[t], af[t]);
            float res = af[t] - __uint_as_float(ah[t]);
            CVT_TF32(al[t], res);
        }
#pragma unroll
        for (int nc = 0; nc < 4; nc++) {
            uint2 b0 = wb2[(kc * 8 + lc) * 36 + nc * 8 + lr];
            uint2 b1 = wb2[(kc * 8 + lc + 4) * 36 + nc * 8 + lr];
            mma_tf32(d[nc][0], d[nc][1], d[nc][2], d[nc][3],
                     ah[0], ah[1], ah[2], ah[3], b0.x, b1.x);
            mma_tf32(d[nc][0], d[nc][1], d[nc][2], d[nc][3],
                     ah[0], ah[1], ah[2], ah[3], b0.y, b1.y);
            mma_tf32(d[nc][0], d[nc][1], d[nc][2], d[nc][3],
                     al[0], al[1], al[2], al[3], b0.x, b1.x);
        }
    }

    // epilogue: D fragment -> g_bias rows
    size_t row = rowbase + arow0;
#pragma unroll
    for (int nc = 0; nc < 4; nc++) {
        int col = nc * 8 + 2 * lc;
        *(float2*)&g_bias[row * NH + col]       = make_float2(d[nc][0], d[nc][1]);
        *(float2*)&g_bias[(row + 8) * NH + col] = make_float2(d[nc][2], d[nc][3]);
    }
}

// ---------------------------------------------------------------------------
// Kernel F: streaming attention + force.  256 threads = 8 warps.
// Block = (4 i-rows, c).  lane = head h, warp w covers j == w (mod 8).
// Merge: per-(ii,h) divide BEFORE reducing over heads (R3 bug fixed).
// ---------------------------------------------------------------------------
__global__ void __launch_bounds__(256, 2) attn_kernel(
    const float* __restrict__ delta, float* __restrict__ out) {
    int c = blockIdx.y;
    int ibase = blockIdx.x * 4;
    int tid = threadIdx.x;
    int w = tid >> 5, h = tid & 31;

    ulonglong2 q[4][4];
#pragma unroll
    for (int ii = 0; ii < 4; ii++) {
        const float* qp = g_q + ((size_t)(c * NN) + ibase + ii) * ED + h * HD;
#pragma unroll
        for (int t = 0; t < 4; t++)
            q[ii][t] = *(const ulonglong2*)(qp + t * 4);
    }

    float l[4]  = {0.f, 0.f, 0.f, 0.f};
    float n0[4] = {0.f, 0.f, 0.f, 0.f};
    float n1[4] = {0.f, 0.f, 0.f, 0.f};
    float n2[4] = {0.f, 0.f, 0.f, 0.f};

    const size_t cb = (size_t)(c * NN) + ibase;
#pragma unroll 2
    for (int j = w; j < NN; j += 8) {
        const float* kp = g_k + ((size_t)(c * NN) + j) * ED + h * HD;
        ulonglong2 k0 = *(const ulonglong2*)(kp + 0);
        ulonglong2 k1 = *(const ulonglong2*)(kp + 4);
        ulonglong2 k2 = *(const ulonglong2*)(kp + 8);
        ulonglong2 k3 = *(const ulonglong2*)(kp + 12);
        float vfv = g_vf[((size_t)(c * NN) + j) * NH + h];
        const float* dp = delta + (cb * NN + j) * 3;
        const float* bp = g_bias + (cb * NN + j) * NH + h;
#pragma unroll
        for (int ii = 0; ii < 4; ii++) {
            unsigned long long a;
            MUL2(a, q[ii][0].x, k0.x);
            FMA2(a, q[ii][0].y, k0.y);
            FMA2(a, q[ii][1].x, k1.x);
            FMA2(a, q[ii][1].y, k1.y);
            FMA2(a, q[ii][2].x, k2.x);
            FMA2(a, q[ii][2].y, k2.y);
            FMA2(a, q[ii][3].x, k3.x);
            FMA2(a, q[ii][3].y, k3.y);
            float lo, hi; UNPACK2(lo, hi, a);
            float z = lo + hi + bp[(size_t)ii * (NN * NH)];
            float we = __expf(z);
            float wv = we * vfv;
            float d0 = dp[ii * (NN * 3) + 0];
            float d1 = dp[ii * (NN * 3) + 1];
            float d2 = dp[ii * (NN * 3) + 2];
            l[ii]  += we;
            n0[ii] += wv * d0;
            n1[ii] += wv * d1;
            n2[ii] += wv * d2;
        }
    }

    __shared__ float ms[8][4][32][4];
#pragma unroll
    for (int ii = 0; ii < 4; ii++)
        *(float4*)&ms[w][ii][h][0] = make_float4(l[ii], n0[ii], n1[ii], n2[ii]);
    __syncthreads();

    if (w < 4) {
        int ii = w;
        float L = 0.f, F0 = 0.f, F1 = 0.f, F2 = 0.f;
#pragma unroll
        for (int ww = 0; ww < 8; ww++) {
            float4 a = *(const float4*)&ms[ww][ii][h][0];
            L += a.x; F0 += a.y; F1 += a.z; F2 += a.w;
        }
        // per-(i, head) normalization BEFORE summing over heads
        float inv = 1.f / L;
        F0 *= inv; F1 *= inv; F2 *= inv;
#pragma unroll
        for (int off = 16; off; off >>= 1) {
            F0 += __shfl_down_sync(0xffffffffu, F0, off);
            F1 += __shfl_down_sync(0xffffffffu, F1, off);
            F2 += __shfl_down_sync(0xffffffffu, F2, off);
        }
        if (h == 0) {
            float* op = out + ((size_t)(c * NN) + ibase + ii) * 3;
            op[0] = F0; op[1] = F1; op[2] = F2;
        }
    }
}

// ---------------------------------------------------------------------------
// Host launch
// ---------------------------------------------------------------------------
extern "C" void kernel_launch(void* const* d_in, const int* in_sizes, int n_in,
                              void* d_out, int out_size) {
    const float* query = (const float*)d_in[0];
    const float* pair  = (const float*)d_in[1];
    const float* delta = (const float*)d_in[2];
    const float* lnqg  = (const float*)d_in[3];
    const float* lnqb  = (const float*)d_in[4];
    const float* lnpg  = (const float*)d_in[5];
    const float* lnpb  = (const float*)d_in[6];
    const float* Wq    = (const float*)d_in[7];
    const float* Wk    = (const float*)d_in[8];
    const float* Wv    = (const float*)d_in[9];
    const float* Wb    = (const float*)d_in[10];
    const float* bb    = (const float*)d_in[11];
    const float* Wf    = (const float*)d_in[12];
    float* out = (float*)d_out;

    cudaFuncSetAttribute(bias_kernel,
                         cudaFuncAttributeMaxDynamicSharedMemorySize, BIAS_SMEM_BYTES);

    ln_q_kernel<<<NC * NN, 128>>>(query, lnqg, lnqb);

    dim3 gg(ED / 64, (NC * NN) / 64, 3);
    qkv_gemm<<<gg, 256>>>(Wq, Wk, Wv);

    vf_kernel<<<(NC * NN * NH) / 256, 256>>>(Wf);

    bias_kernel<<<(NC * NN * NN) / BM, 256, BIAS_SMEM_BYTES>>>(pair, lnpg, lnpb, Wb, bb);

    attn_kernel<<<dim3(NN / 4, NC), 256>>>(delta, out);
}